// round 8
// baseline (speedup 1.0000x reference)
#include <cuda_runtime.h>
#include <math.h>

#define NUM_HEADS    32
#define HEAD_SIZE    128
#define NUM_KV_HEADS 8
#define GRP          4
#define BLK_SZ       16
#define MAX_BLOCKS   64
#define MAX_CTX      1024
#define NUM_SEQS     64
#define SCALE        0.08838834764831845f
#define LOG2E        1.4426950408889634f

#define PART    64                          // tokens per work item
#define MAXP    16                          // max partitions per (s,h)
#define PBLK    4                           // blocks per item
#define NITEMS  (NUM_SEQS * NUM_KV_HEADS * MAXP)   // 8192
#define STAGE_F (2 * PBLK * 2048 + 512)     // K 8192 + V 8192 + q 512 floats
#define NSTG    3

// split-K scratch (device globals: no allocation allowed)
__device__ float g_po[NUM_SEQS * NUM_KV_HEADS * MAXP * GRP * HEAD_SIZE]; // ~17 MB
__device__ float g_pm[NUM_SEQS * NUM_KV_HEADS * MAXP * GRP];
__device__ float g_ps[NUM_SEQS * NUM_KV_HEADS * MAXP * GRP];
__device__ int   g_cnt[NUM_SEQS * NUM_KV_HEADS];   // zero-init; self-resetting

__device__ __forceinline__ unsigned smem_u32(const void* p) {
    return (unsigned)__cvta_generic_to_shared(p);
}
__device__ __forceinline__ void cp16(unsigned dst, const float* src) {
    asm volatile("cp.async.cg.shared.global [%0], [%1], 16;" :: "r"(dst), "l"(src));
}

// stage layout (floats): [0,8192) K 4 blocks, [8192,16384) V 4 blocks, [16384,16896) q
__device__ __forceinline__ void issue_item(int w, float* stg,
                                           const float* __restrict__ q_in,
                                           const float* __restrict__ kcache,
                                           const float* __restrict__ vcache,
                                           const int*   __restrict__ btab,
                                           const int*   sh_ctx, int tid)
{
    const int s = w >> 7, h = (w >> 4) & 7, p = w & 15;
    const int L = sh_ctx[s];
    const int n = min(PART, L - p * PART);          // > 0 (item is active)
    const int b  = tid >> 6;                        // 0..3 : block
    const int t6 = tid & 63;
    if (b * BLK_SZ < n) {
        const int pb = btab[s * MAX_BLOCKS + p * PBLK + b];
        const size_t off = ((size_t)pb * NUM_KV_HEADS + h) * 2048 + t6 * 4;
        const float* ksrc = kcache + off;
        const float* vsrc = vcache + off;
        unsigned kdst = smem_u32(stg + b * 2048 + t6 * 4);
        unsigned vdst = smem_u32(stg + 8192 + b * 2048 + t6 * 4);
        #pragma unroll
        for (int i = 0; i < 8; i++) {
            cp16(kdst + i * 1024, ksrc + i * 256);
            cp16(vdst + i * 1024, vsrc + i * 256);
        }
    }
    if (tid < 128)
        cp16(smem_u32(stg + 16384 + tid * 4),
             q_in + (size_t)s * (NUM_HEADS * HEAD_SIZE) + h * GRP * HEAD_SIZE + tid * 4);
}

__global__ __launch_bounds__(256, 1)
void paged_attn_persist(const float* __restrict__ q_in,
                        const float* __restrict__ knew,
                        const float* __restrict__ vnew,
                        const float* __restrict__ kcache,
                        const float* __restrict__ vcache,
                        const int*   __restrict__ btab,
                        const int*   __restrict__ ctxlen,
                        float*       __restrict__ out)
{
    extern __shared__ float dynsm[];                 // 3 stages

    __shared__ int   sh_ctx[NUM_SEQS];
    __shared__ float sh_p[GRP][PART];
    __shared__ float sh_acc[2][GRP][HEAD_SIZE];
    __shared__ float sh_m[GRP], sh_s[GRP];
    __shared__ float sh_w[MAXP][GRP];
    __shared__ int   sh_win;

    const int tid  = threadIdx.x;
    const int lane = tid & 31;
    const int wid  = tid >> 5;
    const int G    = gridDim.x;

    if (tid < NUM_SEQS) sh_ctx[tid] = ctxlen[tid];
    __syncthreads();

    // deterministic static striding over active items
    int wA = blockIdx.x;
    while (wA < NITEMS && !((wA & 15) * PART < sh_ctx[wA >> 7])) wA += G;
    int wB = (wA < NITEMS) ? wA + G : NITEMS;
    while (wB < NITEMS && !((wB & 15) * PART < sh_ctx[wB >> 7])) wB += G;

    if (wA < NITEMS) issue_item(wA, dynsm,           q_in, kcache, vcache, btab, sh_ctx, tid);
    asm volatile("cp.async.commit_group;");
    if (wB < NITEMS) issue_item(wB, dynsm + STAGE_F, q_in, kcache, vcache, btab, sh_ctx, tid);
    asm volatile("cp.async.commit_group;");

    int buf = 0;
    while (wA < NITEMS) {
        // issue item wC two stages ahead (that stage was consumed last iteration)
        int wC = (wB < NITEMS) ? wB + G : NITEMS;
        while (wC < NITEMS && !((wC & 15) * PART < sh_ctx[wC >> 7])) wC += G;
        int nbuf = buf + 2; if (nbuf >= 3) nbuf -= 3;
        if (wC < NITEMS) issue_item(wC, dynsm + nbuf * STAGE_F, q_in, kcache, vcache, btab, sh_ctx, tid);
        asm volatile("cp.async.commit_group;");

        asm volatile("cp.async.wait_group 2;");      // current stage complete
        __syncthreads();

        // ---- compute item wA from stage buf ----
        const int s = wA >> 7, h = (wA >> 4) & 7, p = wA & 15;
        const int shh = (s << 3) | h;
        const int L  = sh_ctx[s];
        const int t0 = p * PART;
        const int n  = min(PART, L - t0);
        const int nblk = (n + 15) >> 4;
        const int npad = nblk << 4;
        const int np   = (L + PART - 1) / PART;

        const float* kst = dynsm + buf * STAGE_F;
        const float* vst = kst + 8192;
        const float* qst = kst + 16384;

        const float vnd = vnew[(size_t)s * (NUM_KV_HEADS * HEAD_SIZE) + h * HEAD_SIZE + (tid & 127)];

        // Phase 1: scores (warps 0..nblk-1), K from shared (generic ptr covers knew path)
        if (wid < nblk) {
            const int tb   = lane & 15;
            const int half = lane >> 4;
            const int t    = t0 + wid * BLK_SZ + tb;
            const int lt   = wid * BLK_SZ + tb;

            const float* kb;
            int cs;
            if (t == L - 1) {
                kb = knew + (size_t)s * (NUM_KV_HEADS * HEAD_SIZE) + h * HEAD_SIZE + half * 64;
                cs = 8;
            } else {
                kb = kst + wid * 2048 + half * 1024 + tb * 8;
                cs = 128;
            }

            float acc[GRP] = {0.f, 0.f, 0.f, 0.f};
            #pragma unroll
            for (int j = 0; j < 8; j++) {
                float4 k0 = *(const float4*)(kb + j * cs);
                float4 k1 = *(const float4*)(kb + j * cs + 4);
                int d0 = half * 64 + j * 8;
                #pragma unroll
                for (int g = 0; g < GRP; g++) {
                    float4 qa = *(const float4*)&qst[g * 128 + d0];
                    float4 qb = *(const float4*)&qst[g * 128 + d0 + 4];
                    acc[g] += k0.x * qa.x + k0.y * qa.y + k0.z * qa.z + k0.w * qa.w
                            + k1.x * qb.x + k1.y * qb.y + k1.z * qb.z + k1.w * qb.w;
                }
            }
            #pragma unroll
            for (int g = 0; g < GRP; g++)
                acc[g] += __shfl_xor_sync(0xffffffffu, acc[g], 16);

            if (half == 0) {
                #pragma unroll
                for (int g = 0; g < GRP; g++)
                    sh_p[g][lt] = (lt < n) ? acc[g] * SCALE : -1e30f;
            }
        }
        __syncthreads();

        // Phase 2: local softmax stats (4 warps, one head each)
        if (wid < GRP) {
            const int g = wid;
            float m = -1e30f;
            for (int i = lane; i < npad; i += 32) m = fmaxf(m, sh_p[g][i]);
            #pragma unroll
            for (int o = 16; o > 0; o >>= 1) m = fmaxf(m, __shfl_xor_sync(0xffffffffu, m, o));
            float sum = 0.f;
            for (int i = lane; i < npad; i += 32) {
                float e = exp2f((sh_p[g][i] - m) * LOG2E);
                sh_p[g][i] = e;
                sum += e;
            }
            #pragma unroll
            for (int o = 16; o > 0; o >>= 1) sum += __shfl_xor_sync(0xffffffffu, sum, o);
            if (lane == 0) { sh_m[g] = m; sh_s[g] = sum; }
        }
        __syncthreads();

        // Phase 3: partial P@V from shared (unnormalized)
        {
            const int d  = tid & 127;
            const int th = tid >> 7;
            const int rot = (d >> 1) & 3;

            float acc[GRP] = {0.f, 0.f, 0.f, 0.f};
            for (int b = th; b < nblk; b += 2) {
                const float* vb = vst + b * 2048 + d * 16;
                const int lt0 = b * BLK_SZ;
                #pragma unroll
                for (int j = 0; j < 4; j++) {
                    const int jr = (j + rot) & 3;
                    float4 v = *(const float4*)(vb + jr * 4);
                    const int ltj = lt0 + jr * 4;
                    const int o = (L - 1) - (t0 + ltj);   // new-token value override
                    if ((unsigned)o < 4u) {
                        if      (o == 0) v.x = vnd;
                        else if (o == 1) v.y = vnd;
                        else if (o == 2) v.z = vnd;
                        else             v.w = vnd;
                    }
                    #pragma unroll
                    for (int g = 0; g < GRP; g++) {
                        acc[g] += v.x * sh_p[g][ltj + 0];
                        acc[g] += v.y * sh_p[g][ltj + 1];
                        acc[g] += v.z * sh_p[g][ltj + 2];
                        acc[g] += v.w * sh_p[g][ltj + 3];
                    }
                }
            }
            #pragma unroll
            for (int g = 0; g < GRP; g++) sh_acc[th][g][d] = acc[g];
        }
        __syncthreads();

        // write partials
        const size_t base = (size_t)wA * (GRP * HEAD_SIZE);
        for (int i = tid; i < GRP * HEAD_SIZE; i += 256)
            g_po[base + i] = sh_acc[0][i >> 7][i & 127] + sh_acc[1][i >> 7][i & 127];
        if (tid < GRP) {
            g_pm[(size_t)wA * GRP + tid] = sh_m[tid];
            g_ps[(size_t)wA * GRP + tid] = sh_s[tid];
        }

        // fused combine: last item of (s,h) finalizes
        __threadfence();
        if (tid == 0) {
            int old = atomicAdd(&g_cnt[shh], 1);
            sh_win = (old == np - 1);
            if (sh_win) g_cnt[shh] = 0;   // self-reset for graph replay
        }
        __syncthreads();
        if (sh_win) {
            __threadfence();              // acquire all partitions' partials
            if (wid == 0) {               // lane = g + 4*pp0; covers pp0, pp0+8
                const int g   = lane & 3;
                const int pp0 = lane >> 2;
                const int pp1 = pp0 + 8;
                const size_t i0 = ((size_t)shh * MAXP + pp0) * GRP + g;
                const size_t i1 = ((size_t)shh * MAXP + pp1) * GRP + g;
                float m0 = (pp0 < np) ? g_pm[i0] : -1e30f;
                float m1 = (pp1 < np) ? g_pm[i1] : -1e30f;
                float M = fmaxf(m0, m1);
                #pragma unroll
                for (int o = 4; o < 32; o <<= 1) M = fmaxf(M, __shfl_xor_sync(0xffffffffu, M, o));
                float w0 = (pp0 < np) ? exp2f((m0 - M) * LOG2E) : 0.f;
                float w1 = (pp1 < np) ? exp2f((m1 - M) * LOG2E) : 0.f;
                float den = ((pp0 < np) ? w0 * g_ps[i0] : 0.f)
                          + ((pp1 < np) ? w1 * g_ps[i1] : 0.f);
                #pragma unroll
                for (int o = 4; o < 32; o <<= 1) den += __shfl_xor_sync(0xffffffffu, den, o);
                float inv = 1.f / den;
                sh_w[pp0][g] = w0 * inv;
                sh_w[pp1][g] = w1 * inv;
            }
            __syncthreads();
            for (int i = tid; i < GRP * HEAD_SIZE; i += 256) {
                const int g = i >> 7, d = i & 127;
                float acc = 0.f;
                for (int pp = 0; pp < np; pp++)
                    acc += sh_w[pp][g] * g_po[((size_t)shh * MAXP + pp) * (GRP * HEAD_SIZE) + i];
                out[(size_t)s * (NUM_HEADS * HEAD_SIZE) + (h * GRP + g) * HEAD_SIZE + d] = acc;
            }
        }
        __syncthreads();    // all reads of stage buf / statics done before reuse

        wA = wB; wB = wC; buf = buf + 1; if (buf >= 3) buf -= 3;
    }
}

extern "C" void kernel_launch(void* const* d_in, const int* in_sizes, int n_in,
                              void* d_out, int out_size)
{
    const float* query       = (const float*)d_in[0];
    const float* key         = (const float*)d_in[1];
    const float* value       = (const float*)d_in[2];
    const float* key_cache   = (const float*)d_in[3];
    const float* value_cache = (const float*)d_in[4];
    const int*   block_tab   = (const int*)d_in[5];
    const int*   ctx_lens    = (const int*)d_in[6];
    float* out = (float*)d_out;

    int dev = 0;
    cudaGetDevice(&dev);
    int G = 148;
    cudaDeviceGetAttribute(&G, cudaDevAttrMultiProcessorCount, dev);

    const int dyn_smem = NSTG * STAGE_F * (int)sizeof(float);   // 202752 B
    cudaFuncSetAttribute(paged_attn_persist,
                         cudaFuncAttributeMaxDynamicSharedMemorySize, dyn_smem);

    paged_attn_persist<<<G, 256, dyn_smem>>>(
        query, key, value, key_cache, value_cache, block_tab, ctx_lens, out);
}

// round 9
// speedup vs baseline: 2.1848x; 2.1848x over previous
#include <cuda_runtime.h>
#include <math.h>

#define NUM_HEADS    32
#define HEAD_SIZE    128
#define NUM_KV_HEADS 8
#define GRP          4
#define BLK_SZ       16
#define MAX_BLOCKS   64
#define MAX_CTX      1024
#define NUM_SEQS     64
#define SCALE        0.08838834764831845f
#define LOG2E        1.4426950408889634f

#define PART         64                   // tokens per split-K partition
#define MAXP         16                   // max partitions per (s,h)
#define PBLK         4                    // 16-token blocks per partition
#define NITEMS      (NUM_SEQS * NUM_KV_HEADS * MAXP)   // 8192

// split-K scratch (device globals: no allocation allowed)
__device__ float g_po[NITEMS * GRP * HEAD_SIZE];   // ~17 MB
__device__ float g_pm[NITEMS * GRP];
__device__ float g_ps[NITEMS * GRP];
__device__ int   g_cnt[NUM_SEQS * NUM_KV_HEADS];   // zero-init; self-resetting

__device__ __forceinline__ unsigned smem_u32(const void* p) {
    return (unsigned)__cvta_generic_to_shared(p);
}
__device__ __forceinline__ void cp16(unsigned dst, const float* src) {
    asm volatile("cp.async.cg.shared.global [%0], [%1], 16;" :: "r"(dst), "l"(src));
}

__global__ __launch_bounds__(256, 3)
void paged_attn_split(const float* __restrict__ q_in,
                      const float* __restrict__ knew,
                      const float* __restrict__ vnew,
                      const float* __restrict__ kcache,
                      const float* __restrict__ vcache,
                      const int*   __restrict__ btab,
                      const int*   __restrict__ ctxlen,
                      float*       __restrict__ out)
{
    extern __shared__ float dynsm[];
    float* kst = dynsm;            // [PBLK][2048]  32 KB
    float* vst = dynsm + 8192;     // [PBLK][2048]  32 KB
    float* qst = dynsm + 16384;    // [512]          2 KB

    const int bx = blockIdx.x;
    const int s  = bx >> 7;              // sequence
    const int h  = (bx >> 4) & 7;        // kv head
    const int p  = bx & 15;              // partition
    const int sh = (s << 3) | h;

    const int L  = ctxlen[s];
    const int t0 = p * PART;
    if (t0 >= L) return;
    const int np   = (L + PART - 1) / PART;
    const int n    = min(PART, L - t0);
    const int nblk = (n + BLK_SZ - 1) / BLK_SZ;     // <= 4
    const int npad = nblk * BLK_SZ;

    const int tid  = threadIdx.x;
    const int lane = tid & 31;
    const int wid  = tid >> 5;

    __shared__ float sh_p[GRP][PART];            // 1 KB
    __shared__ float sh_acc[2][GRP][HEAD_SIZE];  // 4 KB
    __shared__ float sh_m[GRP], sh_s[GRP];
    __shared__ float sh_w[MAXP][GRP];
    __shared__ int   sh_win;

    // ---- Stage everything via register-free, coalesced cp.async ----
    const int b  = tid >> 6;                     // 0..3: block
    const int t6 = tid & 63;
    const bool bact = (b * BLK_SZ < n);
    size_t coff = 0;
    if (bact) {
        const int pb = btab[s * MAX_BLOCKS + p * PBLK + b];
        coff = ((size_t)pb * NUM_KV_HEADS + h) * 2048 + t6 * 4;
        unsigned kdst = smem_u32(kst + b * 2048 + t6 * 4);
        #pragma unroll
        for (int i = 0; i < 8; i++) cp16(kdst + i * 1024, kcache + coff + i * 256);
    }
    if (tid < 128)
        cp16(smem_u32(qst + tid * 4),
             q_in + (size_t)s * (NUM_HEADS * HEAD_SIZE) + h * GRP * HEAD_SIZE + tid * 4);
    asm volatile("cp.async.commit_group;");      // group 0: K + q
    if (bact) {
        unsigned vdst = smem_u32(vst + b * 2048 + t6 * 4);
        #pragma unroll
        for (int i = 0; i < 8; i++) cp16(vdst + i * 1024, vcache + coff + i * 256);
    }
    asm volatile("cp.async.commit_group;");      // group 1: V

    asm volatile("cp.async.wait_group 1;");      // K + q ready (V still streaming)
    __syncthreads();

    // ---- Phase 1: scores from shared. warp per 16-token block ----
    if (wid < nblk) {
        const int tb   = lane & 15;
        const int half = lane >> 4;
        const int t    = t0 + wid * BLK_SZ + tb;
        const int lt   = wid * BLK_SZ + tb;
        const float* kb = kst + wid * 2048 + half * 1024 + tb * 8;

        float acc[GRP] = {0.f, 0.f, 0.f, 0.f};
        #pragma unroll
        for (int j = 0; j < 8; j++) {
            float4 k0 = *(const float4*)(kb + j * 128);
            float4 k1 = *(const float4*)(kb + j * 128 + 4);
            int d0 = half * 64 + j * 8;
            #pragma unroll
            for (int g = 0; g < GRP; g++) {
                float4 qa = *(const float4*)&qst[g * 128 + d0];
                float4 qb = *(const float4*)&qst[g * 128 + d0 + 4];
                acc[g] += k0.x * qa.x + k0.y * qa.y + k0.z * qa.z + k0.w * qa.w
                        + k1.x * qb.x + k1.y * qb.y + k1.z * qb.z + k1.w * qb.w;
            }
        }

        // new token's key lives in `knew`, not the cache: rare recompute
        if (t == L - 1) {
            const float* kn = knew + (size_t)s * (NUM_KV_HEADS * HEAD_SIZE)
                            + h * HEAD_SIZE + half * 64;
            #pragma unroll
            for (int g = 0; g < GRP; g++) acc[g] = 0.f;
            #pragma unroll
            for (int j = 0; j < 8; j++) {
                float4 k0 = *(const float4*)(kn + j * 8);
                float4 k1 = *(const float4*)(kn + j * 8 + 4);
                int d0 = half * 64 + j * 8;
                #pragma unroll
                for (int g = 0; g < GRP; g++) {
                    float4 qa = *(const float4*)&qst[g * 128 + d0];
                    float4 qb = *(const float4*)&qst[g * 128 + d0 + 4];
                    acc[g] += k0.x * qa.x + k0.y * qa.y + k0.z * qa.z + k0.w * qa.w
                            + k1.x * qb.x + k1.y * qb.y + k1.z * qb.z + k1.w * qb.w;
                }
            }
        }

        #pragma unroll
        for (int g = 0; g < GRP; g++)
            acc[g] += __shfl_xor_sync(0xffffffffu, acc[g], 16);

        if (half == 0) {
            #pragma unroll
            for (int g = 0; g < GRP; g++)
                sh_p[g][lt] = (lt < n) ? acc[g] * SCALE : -1e30f;
        }
    }
    __syncthreads();

    // ---- Phase 2: local softmax stats (4 warps, one head each) ----
    if (wid < GRP) {
        const int g = wid;
        float m = -1e30f;
        for (int i = lane; i < npad; i += 32) m = fmaxf(m, sh_p[g][i]);
        #pragma unroll
        for (int o = 16; o > 0; o >>= 1) m = fmaxf(m, __shfl_xor_sync(0xffffffffu, m, o));
        float sum = 0.f;
        for (int i = lane; i < npad; i += 32) {
            float e = exp2f((sh_p[g][i] - m) * LOG2E);
            sh_p[g][i] = e;
            sum += e;
        }
        #pragma unroll
        for (int o = 16; o > 0; o >>= 1) sum += __shfl_xor_sync(0xffffffffu, sum, o);
        if (lane == 0) { sh_m[g] = m; sh_s[g] = sum; }
    }
    asm volatile("cp.async.wait_group 0;");      // V ready
    __syncthreads();

    // ---- Phase 3: partial P@V from shared (unnormalized) ----
    {
        const int d  = tid & 127;
        const int th = tid >> 7;
        const float vnd = vnew[(size_t)s * (NUM_KV_HEADS * HEAD_SIZE) + h * HEAD_SIZE + d];
        const int rot = (d >> 1) & 3;            // bank-conflict-free rotation

        float acc[GRP] = {0.f, 0.f, 0.f, 0.f};
        for (int bb = th; bb < nblk; bb += 2) {
            const float* vb = vst + bb * 2048 + d * 16;
            const int lt0 = bb * BLK_SZ;
            #pragma unroll
            for (int j = 0; j < 4; j++) {
                const int jr = (j + rot) & 3;
                float4 v = *(const float4*)(vb + jr * 4);
                const int ltj = lt0 + jr * 4;
                const int o = (L - 1) - (t0 + ltj);   // new-token value override
                if ((unsigned)o < 4u) {
                    if      (o == 0) v.x = vnd;
                    else if (o == 1) v.y = vnd;
                    else if (o == 2) v.z = vnd;
                    else             v.w = vnd;
                }
                #pragma unroll
                for (int g = 0; g < GRP; g++) {
                    acc[g] += v.x * sh_p[g][ltj + 0];
                    acc[g] += v.y * sh_p[g][ltj + 1];
                    acc[g] += v.z * sh_p[g][ltj + 2];
                    acc[g] += v.w * sh_p[g][ltj + 3];
                }
            }
        }
        #pragma unroll
        for (int g = 0; g < GRP; g++) sh_acc[th][g][d] = acc[g];
    }
    __syncthreads();

    // ---- write partials ----
    const size_t base = ((size_t)bx) * (GRP * HEAD_SIZE);
    for (int i = tid; i < GRP * HEAD_SIZE; i += 256)
        g_po[base + i] = sh_acc[0][i >> 7][i & 127] + sh_acc[1][i >> 7][i & 127];
    if (tid < GRP) {
        g_pm[(size_t)bx * GRP + tid] = sh_m[tid];
        g_ps[(size_t)bx * GRP + tid] = sh_s[tid];
    }

    // ---- fused combine: last CTA for (s,h) finalizes ----
    __threadfence();
    if (tid == 0) {
        int old = atomicAdd(&g_cnt[sh], 1);
        sh_win = (old == np - 1);
        if (sh_win) g_cnt[sh] = 0;   // self-reset for graph replay
    }
    __syncthreads();
    if (!sh_win) return;
    __threadfence();                  // acquire: see all partitions' partials

    // one warp computes combine weights: lane = g + 4*pp0; covers pp0 and pp0+8
    if (wid == 0) {
        const int g   = lane & 3;
        const int pp0 = lane >> 2;
        const int pp1 = pp0 + 8;
        const size_t i0 = ((size_t)sh * MAXP + pp0) * GRP + g;
        const size_t i1 = ((size_t)sh * MAXP + pp1) * GRP + g;
        float m0 = (pp0 < np) ? g_pm[i0] : -1e30f;
        float m1 = (pp1 < np) ? g_pm[i1] : -1e30f;
        float M = fmaxf(m0, m1);
        #pragma unroll
        for (int o = 4; o < 32; o <<= 1) M = fmaxf(M, __shfl_xor_sync(0xffffffffu, M, o));
        float w0 = (pp0 < np) ? exp2f((m0 - M) * LOG2E) : 0.f;
        float w1 = (pp1 < np) ? exp2f((m1 - M) * LOG2E) : 0.f;
        float den = ((pp0 < np) ? w0 * g_ps[i0] : 0.f)
                  + ((pp1 < np) ? w1 * g_ps[i1] : 0.f);
        #pragma unroll
        for (int o = 4; o < 32; o <<= 1) den += __shfl_xor_sync(0xffffffffu, den, o);
        float inv = 1.f / den;
        sh_w[pp0][g] = w0 * inv;
        sh_w[pp1][g] = w1 * inv;
    }
    __syncthreads();

    for (int i = tid; i < GRP * HEAD_SIZE; i += 256) {
        const int g = i >> 7, d = i & 127;
        float acc = 0.f;
        for (int pp = 0; pp < np; pp++)
            acc += sh_w[pp][g] * g_po[((size_t)sh * MAXP + pp) * (GRP * HEAD_SIZE) + i];
        out[(size_t)s * (NUM_HEADS * HEAD_SIZE) + (h * GRP + g) * HEAD_SIZE + d] = acc;
    }
}

extern "C" void kernel_launch(void* const* d_in, const int* in_sizes, int n_in,
                              void* d_out, int out_size)
{
    const float* query       = (const float*)d_in[0];
    const float* key         = (const float*)d_in[1];
    const float* value       = (const float*)d_in[2];
    const float* key_cache   = (const float*)d_in[3];
    const float* value_cache = (const float*)d_in[4];
    const int*   block_tab   = (const int*)d_in[5];
    const int*   ctx_lens    = (const int*)d_in[6];
    float* out = (float*)d_out;

    const int dyn_smem = (2 * PBLK * 2048 + 512) * (int)sizeof(float);  // 67584 B
    cudaFuncSetAttribute(paged_attn_split,
                         cudaFuncAttributeMaxDynamicSharedMemorySize, dyn_smem);

    paged_attn_split<<<NITEMS, 256, dyn_smem>>>(
        query, key, value, key_cache, value_cache, block_tab, ctx_lens, out);
}

// round 10
// speedup vs baseline: 4.4668x; 2.0445x over previous
#include <cuda_runtime.h>
#include <math.h>

#define NUM_HEADS    32
#define HEAD_SIZE    128
#define NUM_KV_HEADS 8
#define GRP          4
#define BLK_SZ       16
#define MAX_BLOCKS   64
#define MAX_CTX      1024
#define NUM_SEQS     64
#define SCALE        0.08838834764831845f
#define LOG2E        1.4426950408889634f

#define PART         128                  // tokens per split-K partition
#define MAXP         (MAX_CTX / PART)     // 8
#define PBLK         (PART / BLK_SZ)      // 8 blocks per partition

// split-K scratch (device globals: no allocation allowed)
__device__ float g_po[NUM_SEQS * NUM_KV_HEADS * MAXP * GRP * HEAD_SIZE]; // 8 MB
__device__ float g_pm[NUM_SEQS * NUM_KV_HEADS * MAXP * GRP];
__device__ float g_ps[NUM_SEQS * NUM_KV_HEADS * MAXP * GRP];
__device__ int   g_cnt[NUM_SEQS * NUM_KV_HEADS];   // zero-init; self-resetting

__device__ __forceinline__ float4 ldcs4(const float* p) {
    return __ldcs((const float4*)p);
}

__global__ __launch_bounds__(256, 4)
void paged_attn_split(const float* __restrict__ q_in,
                      const float* __restrict__ knew,
                      const float* __restrict__ vnew,
                      const float* __restrict__ kcache,
                      const float* __restrict__ vcache,
                      const int*   __restrict__ btab,
                      const int*   __restrict__ ctxlen,
                      float*       __restrict__ out)
{
    const int bx = blockIdx.x;
    const int s  = bx >> 6;              // sequence
    const int h  = (bx >> 3) & 7;        // kv head
    const int p  = bx & 7;               // partition
    const int sh = (s << 3) | h;

    const int L  = ctxlen[s];
    const int t0 = p * PART;
    if (t0 >= L) return;
    const int np   = (L + PART - 1) / PART;
    const int t1   = min(L, t0 + PART);
    const int n    = t1 - t0;
    const int nblk = (n + BLK_SZ - 1) / BLK_SZ;     // 1..8
    const int npad = nblk * BLK_SZ;

    const int tid  = threadIdx.x;
    const int lane = tid & 31;
    const int wid  = tid >> 5;

    __shared__ float sh_q[GRP][HEAD_SIZE];       // 2 KB
    __shared__ float sh_p[GRP][PART];            // 2 KB
    __shared__ float sh_acc[GRP][HEAD_SIZE];     // 2 KB
    __shared__ float sh_m[GRP], sh_s[GRP];
    __shared__ float sh_w[MAXP][GRP];
    __shared__ int   sh_btab[PBLK];
    __shared__ int   sh_win;

    if (tid < PBLK) sh_btab[tid] = btab[s * MAX_BLOCKS + p * PBLK + tid];
    for (int i = tid; i < GRP * HEAD_SIZE; i += 256) {
        int g = i >> 7, d = i & 127;
        sh_q[g][d] = q_in[(size_t)s * (NUM_HEADS * HEAD_SIZE) + (h * GRP + g) * HEAD_SIZE + d];
    }
    __syncthreads();

    // ---- Phase 1: warp per 16-token block scores K (coalesced LDG) ----
    if (wid < nblk) {
        const int tb   = lane & 15;
        const int half = lane >> 4;
        const int pb   = sh_btab[wid];
        const int t    = t0 + wid * BLK_SZ + tb;
        const int lt   = wid * BLK_SZ + tb;

        const float* kb;
        int cs;
        if (t == L - 1) {
            kb = knew + (size_t)s * (NUM_KV_HEADS * HEAD_SIZE) + h * HEAD_SIZE + half * 64;
            cs = 8;
        } else {
            kb = kcache + ((size_t)pb * NUM_KV_HEADS + h) * 2048 + (size_t)half * 1024 + tb * 8;
            cs = 128;
        }

        float acc[GRP] = {0.f, 0.f, 0.f, 0.f};
        #pragma unroll
        for (int j = 0; j < 8; j++) {
            float4 k0 = ldcs4(kb + j * cs);
            float4 k1 = ldcs4(kb + j * cs + 4);
            int d0 = half * 64 + j * 8;
            #pragma unroll
            for (int g = 0; g < GRP; g++) {
                float4 qa = *(const float4*)&sh_q[g][d0];
                float4 qb = *(const float4*)&sh_q[g][d0 + 4];
                acc[g] += k0.x * qa.x + k0.y * qa.y + k0.z * qa.z + k0.w * qa.w
                        + k1.x * qb.x + k1.y * qb.y + k1.z * qb.z + k1.w * qb.w;
            }
        }
        #pragma unroll
        for (int g = 0; g < GRP; g++)
            acc[g] += __shfl_xor_sync(0xffffffffu, acc[g], 16);

        if (half == 0) {
            #pragma unroll
            for (int g = 0; g < GRP; g++)
                sh_p[g][lt] = (lt < n) ? acc[g] * SCALE : -1e30f;
        }
    } else {
        // zero-pad probabilities for inactive blocks (phase 3 runs fixed 8 blocks)
        const int tb = lane & 15;
        if (lane < 16) {
            const int lt = wid * BLK_SZ + tb;
            #pragma unroll
            for (int g = 0; g < GRP; g++) sh_p[g][lt] = 0.f;
        }
    }
    __syncthreads();

    // ---- Phase 2: local softmax stats (4 warps, one head each) ----
    if (wid < GRP) {
        const int g = wid;
        float m = -1e30f;
        for (int i = lane; i < npad; i += 32) m = fmaxf(m, sh_p[g][i]);
        #pragma unroll
        for (int o = 16; o > 0; o >>= 1) m = fmaxf(m, __shfl_xor_sync(0xffffffffu, m, o));
        float sum = 0.f;
        for (int i = lane; i < npad; i += 32) {
            float e = exp2f((sh_p[g][i] - m) * LOG2E);
            sh_p[g][i] = e;
            sum += e;
        }
        #pragma unroll
        for (int o = 16; o > 0; o >>= 1) sum += __shfl_xor_sync(0xffffffffu, sum, o);
        if (lane == 0) { sh_m[g] = m; sh_s[g] = sum; }
    }
    __syncthreads();

    // ---- Phase 3: partial P@V, fully coalesced.
    //      lane = (j = token quad, d-low); warp covers 8 consecutive d x 4 quads.
    //      Each thread: d0 = 8*wid + (lane>>2) and d0+64, all 8 blocks.
    {
        const int j  = lane & 3;
        const int d0 = (wid << 3) + (lane >> 2);     // 0..63
        const int d1 = d0 + 64;
        const float vnd0 = vnew[(size_t)s * (NUM_KV_HEADS * HEAD_SIZE) + h * HEAD_SIZE + d0];
        const float vnd1 = vnew[(size_t)s * (NUM_KV_HEADS * HEAD_SIZE) + h * HEAD_SIZE + d1];

        float acc0[GRP] = {0.f, 0.f, 0.f, 0.f};
        float acc1[GRP] = {0.f, 0.f, 0.f, 0.f};
        #pragma unroll
        for (int b = 0; b < PBLK; b++) {
            const int bc = min(b, nblk - 1);          // clamp: p==0 there
            const float* vb = vcache + ((size_t)sh_btab[bc] * NUM_KV_HEADS + h) * 2048;
            float4 v0 = ldcs4(vb + d0 * 16 + j * 4);
            float4 v1 = ldcs4(vb + d1 * 16 + j * 4);
            const int ltj = b * BLK_SZ + j * 4;
            const int o = (L - 1) - (t0 + ltj);       // new-token value override
            if ((unsigned)o < 4u) {
                if      (o == 0) { v0.x = vnd0; v1.x = vnd1; }
                else if (o == 1) { v0.y = vnd0; v1.y = vnd1; }
                else if (o == 2) { v0.z = vnd0; v1.z = vnd1; }
                else             { v0.w = vnd0; v1.w = vnd1; }
            }
            #pragma unroll
            for (int g = 0; g < GRP; g++) {
                float4 pr = *(const float4*)&sh_p[g][ltj];
                acc0[g] += v0.x * pr.x + v0.y * pr.y + v0.z * pr.z + v0.w * pr.w;
                acc1[g] += v1.x * pr.x + v1.y * pr.y + v1.z * pr.z + v1.w * pr.w;
            }
        }
        // reduce over token quads (lane bits 0-1)
        #pragma unroll
        for (int g = 0; g < GRP; g++) {
            acc0[g] += __shfl_xor_sync(0xffffffffu, acc0[g], 1);
            acc0[g] += __shfl_xor_sync(0xffffffffu, acc0[g], 2);
            acc1[g] += __shfl_xor_sync(0xffffffffu, acc1[g], 1);
            acc1[g] += __shfl_xor_sync(0xffffffffu, acc1[g], 2);
        }
        if (j == 0) {
            #pragma unroll
            for (int g = 0; g < GRP; g++) {
                sh_acc[g][d0] = acc0[g];
                sh_acc[g][d1] = acc1[g];
            }
        }
    }
    __syncthreads();

    // ---- write partials ----
    const size_t base = ((size_t)bx) * (GRP * HEAD_SIZE);
    for (int i = tid; i < GRP * HEAD_SIZE; i += 256)
        g_po[base + i] = sh_acc[i >> 7][i & 127];
    if (tid < GRP) {
        g_pm[(size_t)bx * GRP + tid] = sh_m[tid];
        g_ps[(size_t)bx * GRP + tid] = sh_s[tid];
    }

    // ---- fused combine: last CTA for (s,h) finalizes ----
    __threadfence();
    if (tid == 0) {
        int old = atomicAdd(&g_cnt[sh], 1);
        sh_win = (old == np - 1);
        if (sh_win) g_cnt[sh] = 0;   // self-reset for graph replay
    }
    __syncthreads();
    if (!sh_win) return;
    __threadfence();                  // acquire: see all partitions' partials

    // one warp computes combine weights: lane = g + 4*pp
    if (wid == 0) {
        const int g  = lane & 3;
        const int pp = lane >> 2;
        const bool act = (pp < np);
        const size_t idx = ((size_t)sh * MAXP + pp) * GRP + g;
        float m  = act ? g_pm[idx] : -1e30f;
        float M = m;
        #pragma unroll
        for (int o = 4; o < 32; o <<= 1) M = fmaxf(M, __shfl_xor_sync(0xffffffffu, M, o));
        float w  = act ? exp2f((m - M) * LOG2E) : 0.f;
        float den = act ? w * g_ps[idx] : 0.f;
        #pragma unroll
        for (int o = 4; o < 32; o <<= 1) den += __shfl_xor_sync(0xffffffffu, den, o);
        sh_w[pp][g] = w / den;
    }
    __syncthreads();

    for (int i = tid; i < GRP * HEAD_SIZE; i += 256) {
        const int g = i >> 7, d = i & 127;
        float acc = 0.f;
        for (int pp = 0; pp < np; pp++)
            acc += sh_w[pp][g] * g_po[((size_t)sh * MAXP + pp) * (GRP * HEAD_SIZE) + i];
        out[(size_t)s * (NUM_HEADS * HEAD_SIZE) + (h * GRP + g) * HEAD_SIZE + d] = acc;
    }
}

extern "C" void kernel_launch(void* const* d_in, const int* in_sizes, int n_in,
                              void* d_out, int out_size)
{
    const float* query       = (const float*)d_in[0];
    const float* key         = (const float*)d_in[1];
    const float* value       = (const float*)d_in[2];
    const float* key_cache   = (const float*)d_in[3];
    const float* value_cache = (const float*)d_in[4];
    const int*   block_tab   = (const int*)d_in[5];
    const int*   ctx_lens    = (const int*)d_in[6];
    float* out = (float*)d_out;

    paged_attn_split<<<NUM_SEQS * NUM_KV_HEADS * MAXP, 256>>>(
        query, key, value, key_cache, value_cache, block_tab, ctx_lens, out);
}